// round 6
// baseline (speedup 1.0000x reference)
#include <cuda_runtime.h>
#include <cuda_bf16.h>
#include <cstdint>

// Problem constants
#define BATCH 2
#define CCH   256
#define NPOS  4096      // 64*64
#define HEADS 8
#define HDIM  32
#define GROUPS 32
#define CPG   8         // channels per group
#define GN_EPS 1e-5f
#define ATT_SCALE 0.17677669529663687f  // 1/sqrt(32)

// ---------------- scratch (device globals; no runtime allocation) ----------------
__device__ __nv_bfloat16 g_XT[2][BATCH][NPOS][CCH];      // [src(q/k)][b][n][c]  8 MB
__device__ __nv_bfloat16 g_W[3][CCH][CCH];               // q,k,v weights bf16
__device__ __nv_bfloat16 g_Q[BATCH][HEADS][NPOS][HDIM];  // 4 MB
__device__ __nv_bfloat16 g_K[BATCH][HEADS][NPOS][HDIM];  // 4 MB
__device__ __nv_bfloat16 g_V[BATCH][HEADS][HDIM][NPOS];  // transposed  4 MB
__device__ float g_AO[BATCH][CCH][NPOS];                 // attention out 8 MB
__device__ float g_Z[BATCH][CCH][NPOS];                  // residual+proj 8 MB
__device__ float2 g_part[BATCH*GROUPS][8];               // partial (sum,sumsq)
__device__ float2 g_stats[BATCH*GROUPS];                 // (mean, rstd)

// ---------------- helpers ----------------
__device__ __forceinline__ uint32_t pack_bf16x2(float lo, float hi) {
    uint32_t r;
    asm("cvt.rn.bf16x2.f32 %0, %1, %2;" : "=r"(r) : "f"(hi), "f"(lo));
    return r;
}

#define MMA_BF16(d, a0,a1,a2,a3, b0,b1)                                   \
    asm volatile("mma.sync.aligned.m16n8k16.row.col.f32.bf16.bf16.f32 "   \
        "{%0,%1,%2,%3}, {%4,%5,%6,%7}, {%8,%9}, {%0,%1,%2,%3};"           \
        : "+f"(d[0]), "+f"(d[1]), "+f"(d[2]), "+f"(d[3])                  \
        : "r"(a0), "r"(a1), "r"(a2), "r"(a3), "r"(b0), "r"(b1))

// ---------------- kernel 1: transpose + convert inputs to bf16 ----------------
// x[b][c][n] fp32 -> g_XT[src][b][n][c] bf16
__global__ void prep_transpose(const float* __restrict__ xq, const float* __restrict__ xk) {
    __shared__ float tile[32][33];
    int src = blockIdx.z >> 1;
    int b   = blockIdx.z & 1;
    const float* x = src ? xk : xq;
    int n0 = blockIdx.x * 32, c0 = blockIdx.y * 32;
    #pragma unroll
    for (int i = 0; i < 32; i += 8)
        tile[threadIdx.y + i][threadIdx.x] =
            x[(b * CCH + c0 + threadIdx.y + i) * NPOS + n0 + threadIdx.x];
    __syncthreads();
    #pragma unroll
    for (int i = 0; i < 32; i += 8)
        g_XT[src][b][n0 + threadIdx.y + i][c0 + threadIdx.x] =
            __float2bfloat16(tile[threadIdx.x][threadIdx.y + i]);
}

// ---------------- kernel 2: convert weights to bf16 ----------------
__global__ void prep_weights(const float* __restrict__ qw,
                             const float* __restrict__ kw,
                             const float* __restrict__ vw) {
    int idx = blockIdx.x * 256 + threadIdx.x;   // grid 768 -> 196608 elements
    int which = idx >> 16;
    int r = idx & 65535;
    const float* w = (which == 0) ? qw : (which == 1) ? kw : vw;
    ((__nv_bfloat16*)g_W)[idx] = __float2bfloat16(w[r]);
}

// ---------------- kernel 3: QKV projection GEMM (bf16 mma) ----------------
// D[n][ch] = sum_c XT[n][c] * W[ch][c] + bias[ch]
__global__ __launch_bounds__(128) void qkv_gemm(const float* __restrict__ qb,
                                                const float* __restrict__ kb,
                                                const float* __restrict__ vb) {
    int p = blockIdx.y;           // 0=Q,1=K,2=V
    int b = blockIdx.z;
    int nb = blockIdx.x >> 2;     // 64 n-blocks of 64
    int cb = blockIdx.x & 3;      // 4 ch-blocks of 64
    int n0 = nb * 64, ch0 = cb * 64;
    const __nv_bfloat16* XT = &g_XT[(p == 0) ? 0 : 1][b][0][0];
    const __nv_bfloat16* W  = &g_W[p][0][0];
    const float* bias = (p == 0) ? qb : (p == 1) ? kb : vb;

    __shared__ __align__(16) __nv_bfloat16 As[64][40];  // rows n, pad to 80B
    __shared__ __align__(16) __nv_bfloat16 Bs[64][40];  // rows ch

    int tid = threadIdx.x;
    int w = tid >> 5, lane = tid & 31, g = lane >> 2, t = lane & 3;
    float acc[8][4] = {};

    for (int kk0 = 0; kk0 < 256; kk0 += 32) {
        #pragma unroll
        for (int it = 0; it < 2; it++) {
            int id2 = tid + it * 128;            // 0..255
            int r = id2 >> 2, c16 = id2 & 3;
            *(uint4*)&As[r][c16 * 8] = *(const uint4*)&XT[(n0 + r) * 256 + kk0 + c16 * 8];
            *(uint4*)&Bs[r][c16 * 8] = *(const uint4*)&W[(ch0 + r) * 256 + kk0 + c16 * 8];
        }
        __syncthreads();
        int m0 = w * 16;
        #pragma unroll
        for (int ks = 0; ks < 32; ks += 16) {
            int c = ks + 2 * t;
            uint32_t a0 = *(uint32_t*)&As[m0 + g][c];
            uint32_t a1 = *(uint32_t*)&As[m0 + g + 8][c];
            uint32_t a2 = *(uint32_t*)&As[m0 + g][c + 8];
            uint32_t a3 = *(uint32_t*)&As[m0 + g + 8][c + 8];
            #pragma unroll
            for (int j = 0; j < 8; j++) {
                uint32_t b0 = *(uint32_t*)&Bs[j * 8 + g][c];
                uint32_t b1 = *(uint32_t*)&Bs[j * 8 + g][c + 8];
                MMA_BF16(acc[j], a0, a1, a2, a3, b0, b1);
            }
        }
        __syncthreads();
    }

    // epilogue: add bias, write to head-layout scratch
    #pragma unroll
    for (int j = 0; j < 8; j++) {
        int ch = ch0 + j * 8 + 2 * t;
        float b0f = __ldg(&bias[ch]);
        float b1f = __ldg(&bias[ch + 1]);
        #pragma unroll
        for (int h2 = 0; h2 < 2; h2++) {
            int row = n0 + w * 16 + g + h2 * 8;
            float v0 = acc[j][h2 * 2 + 0] + b0f;
            float v1 = acc[j][h2 * 2 + 1] + b1f;
            int hh = ch >> 5, dd = ch & 31;
            if (p == 0) {
                *(uint32_t*)&g_Q[b][hh][row][dd] = pack_bf16x2(v0, v1);
            } else if (p == 1) {
                *(uint32_t*)&g_K[b][hh][row][dd] = pack_bf16x2(v0, v1);
            } else {
                g_V[b][hh][dd][row]     = __float2bfloat16(v0);
                g_V[b][hh][dd + 1][row] = __float2bfloat16(v1);
            }
        }
    }
}

// ---------------- kernel 4: flash attention (bf16 mma, online softmax) ----------------
__global__ __launch_bounds__(128) void flash_attn() {
    int nb = blockIdx.x, h = blockIdx.y, b = blockIdx.z;
    __shared__ __align__(16) __nv_bfloat16 Ks[64][40];   // keys x d (pad 80B)
    __shared__ __align__(16) __nv_bfloat16 Vts[32][72];  // d x keys (pad 144B)

    int tid = threadIdx.x;
    int w = tid >> 5, lane = tid & 31, g = lane >> 2, t = lane & 3;
    const __nv_bfloat16* Qg = &g_Q[b][h][0][0];
    const __nv_bfloat16* Kg = &g_K[b][h][0][0];
    const __nv_bfloat16* Vg = &g_V[b][h][0][0];
    int m0 = nb * 64 + w * 16;

    // Q A-fragments (k = 0..31 in two 16-steps), loaded once from global
    uint32_t qa[2][4];
    #pragma unroll
    for (int ks = 0; ks < 2; ks++) {
        int c = ks * 16 + 2 * t;
        qa[ks][0] = *(const uint32_t*)&Qg[(m0 + g) * 32 + c];
        qa[ks][1] = *(const uint32_t*)&Qg[(m0 + g + 8) * 32 + c];
        qa[ks][2] = *(const uint32_t*)&Qg[(m0 + g) * 32 + c + 8];
        qa[ks][3] = *(const uint32_t*)&Qg[(m0 + g + 8) * 32 + c + 8];
    }

    float o[4][4] = {};
    float mrow[2] = {-1e30f, -1e30f};
    float lrow[2] = {0.f, 0.f};

    for (int kt = 0; kt < 64; kt++) {
        int k0 = kt * 64;
        // cooperative loads: K tile 64x32 (256 uint4) + Vt tile 32x64 (256 uint4)
        #pragma unroll
        for (int it = 0; it < 2; it++) {
            int id2 = tid + it * 128;
            int r = id2 >> 2, c16 = id2 & 3;
            *(uint4*)&Ks[r][c16 * 8] = *(const uint4*)&Kg[(k0 + r) * 32 + c16 * 8];
            int rv = id2 >> 3, cv = id2 & 7;
            *(uint4*)&Vts[rv][cv * 8] = *(const uint4*)&Vg[rv * NPOS + k0 + cv * 8];
        }
        __syncthreads();

        // S = Q K^T  (16 rows x 64 keys per warp)
        float s[8][4] = {};
        #pragma unroll
        for (int ks = 0; ks < 2; ks++) {
            int c = ks * 16 + 2 * t;
            #pragma unroll
            for (int j = 0; j < 8; j++) {
                uint32_t b0 = *(uint32_t*)&Ks[j * 8 + g][c];
                uint32_t b1 = *(uint32_t*)&Ks[j * 8 + g][c + 8];
                MMA_BF16(s[j], qa[ks][0], qa[ks][1], qa[ks][2], qa[ks][3], b0, b1);
            }
        }
        #pragma unroll
        for (int j = 0; j < 8; j++)
            #pragma unroll
            for (int i = 0; i < 4; i++) s[j][i] *= ATT_SCALE;

        // online softmax per row-half (rows g and g+8)
        #pragma unroll
        for (int r = 0; r < 2; r++) {
            float mx = -1e30f;
            #pragma unroll
            for (int j = 0; j < 8; j++)
                mx = fmaxf(mx, fmaxf(s[j][2 * r], s[j][2 * r + 1]));
            mx = fmaxf(mx, __shfl_xor_sync(0xffffffffu, mx, 1));
            mx = fmaxf(mx, __shfl_xor_sync(0xffffffffu, mx, 2));
            float mnew = fmaxf(mrow[r], mx);
            float corr = __expf(mrow[r] - mnew);
            mrow[r] = mnew;
            float ls = 0.f;
            #pragma unroll
            for (int j = 0; j < 8; j++) {
                s[j][2 * r]     = __expf(s[j][2 * r] - mnew);
                s[j][2 * r + 1] = __expf(s[j][2 * r + 1] - mnew);
                ls += s[j][2 * r] + s[j][2 * r + 1];
            }
            ls += __shfl_xor_sync(0xffffffffu, ls, 1);
            ls += __shfl_xor_sync(0xffffffffu, ls, 2);
            lrow[r] = lrow[r] * corr + ls;
            #pragma unroll
            for (int dt = 0; dt < 4; dt++) {
                o[dt][2 * r]     *= corr;
                o[dt][2 * r + 1] *= corr;
            }
        }

        // O += P V   (P C-frags repacked register-locally into A-frags)
        #pragma unroll
        for (int kk = 0; kk < 4; kk++) {
            int j0 = kk * 2;
            uint32_t pa0 = pack_bf16x2(s[j0][0], s[j0][1]);
            uint32_t pa1 = pack_bf16x2(s[j0][2], s[j0][3]);
            uint32_t pa2 = pack_bf16x2(s[j0 + 1][0], s[j0 + 1][1]);
            uint32_t pa3 = pack_bf16x2(s[j0 + 1][2], s[j0 + 1][3]);
            int c = kk * 16 + 2 * t;
            #pragma unroll
            for (int dt = 0; dt < 4; dt++) {
                uint32_t b0 = *(uint32_t*)&Vts[dt * 8 + g][c];
                uint32_t b1 = *(uint32_t*)&Vts[dt * 8 + g][c + 8];
                MMA_BF16(o[dt], pa0, pa1, pa2, pa3, b0, b1);
            }
        }
        __syncthreads();
    }

    // normalize and write to channel-major fp32 scratch
    float inv0 = 1.f / lrow[0], inv1 = 1.f / lrow[1];
    #pragma unroll
    for (int dt = 0; dt < 4; dt++) {
        int ch = h * 32 + dt * 8 + 2 * t;
        int n = m0 + g;
        g_AO[b][ch][n]         = o[dt][0] * inv0;
        g_AO[b][ch + 1][n]     = o[dt][1] * inv0;
        g_AO[b][ch][n + 8]     = o[dt][2] * inv1;
        g_AO[b][ch + 1][n + 8] = o[dt][3] * inv1;
    }
}

// ---------------- kernel 5: out-proj + residual + partial GN stats ----------------
__global__ __launch_bounds__(256) void proj_gn_partial(const float* __restrict__ qf,
                                                       const float* __restrict__ ow,
                                                       const float* __restrict__ ob) {
    int ck = blockIdx.x;    // 8 spatial chunks of 512
    int gr = blockIdx.y;    // 32 groups
    int b  = blockIdx.z;
    __shared__ __align__(16) float ows_t[256][8];  // [i][c]
    int tid = threadIdx.x;
    for (int i = tid; i < 2048; i += 256)
        ows_t[i & 255][i >> 8] = ow[(gr * 8 + (i >> 8)) * 256 + (i & 255)];
    __syncthreads();

    int n1 = ck * 512 + tid, n2 = n1 + 256;
    float acc0[8] = {}, acc1[8] = {};
    const float* aob = &g_AO[b][0][0];
    const float4* ows4 = (const float4*)ows_t;
    #pragma unroll 4
    for (int i = 0; i < 256; i++) {
        float a1 = aob[i * NPOS + n1];
        float a2 = aob[i * NPOS + n2];
        float4 w0 = ows4[i * 2];
        float4 w1 = ows4[i * 2 + 1];
        acc0[0] += w0.x * a1; acc0[1] += w0.y * a1; acc0[2] += w0.z * a1; acc0[3] += w0.w * a1;
        acc0[4] += w1.x * a1; acc0[5] += w1.y * a1; acc0[6] += w1.z * a1; acc0[7] += w1.w * a1;
        acc1[0] += w0.x * a2; acc1[1] += w0.y * a2; acc1[2] += w0.z * a2; acc1[3] += w0.w * a2;
        acc1[4] += w1.x * a2; acc1[5] += w1.y * a2; acc1[6] += w1.z * a2; acc1[7] += w1.w * a2;
    }

    float sum = 0.f, sq = 0.f;
    #pragma unroll
    for (int c = 0; c < 8; c++) {
        int ch = gr * 8 + c;
        float bb = __ldg(&ob[ch]);
        float z1 = qf[(b * CCH + ch) * NPOS + n1] + acc0[c] + bb;
        float z2 = qf[(b * CCH + ch) * NPOS + n2] + acc1[c] + bb;
        g_Z[b][ch][n1] = z1;
        g_Z[b][ch][n2] = z2;
        sum += z1 + z2;
        sq  += z1 * z1 + z2 * z2;
    }
    // block reduce
    #pragma unroll
    for (int off = 16; off; off >>= 1) {
        sum += __shfl_xor_sync(0xffffffffu, sum, off);
        sq  += __shfl_xor_sync(0xffffffffu, sq, off);
    }
    __shared__ float2 wred[8];
    if ((tid & 31) == 0) wred[tid >> 5] = make_float2(sum, sq);
    __syncthreads();
    if (tid == 0) {
        float s = 0.f, q = 0.f;
        #pragma unroll
        for (int i = 0; i < 8; i++) { s += wred[i].x; q += wred[i].y; }
        g_part[b * GROUPS + gr][ck] = make_float2(s, q);
    }
}

// ---------------- kernel 6: finalize GN stats ----------------
__global__ void gn_stats() {
    int bg = threadIdx.x;
    if (bg < BATCH * GROUPS) {
        float s = 0.f, q = 0.f;
        #pragma unroll
        for (int c = 0; c < 8; c++) { float2 p = g_part[bg][c]; s += p.x; q += p.y; }
        const float invM = 1.f / 32768.f;
        float mean = s * invM;
        float var = q * invM - mean * mean;
        g_stats[bg] = make_float2(mean, rsqrtf(var + GN_EPS));
    }
}

// ---------------- kernel 7: apply GN ----------------
__global__ __launch_bounds__(256) void gn_apply(float* __restrict__ out,
                                                const float* __restrict__ gw,
                                                const float* __restrict__ gb) {
    int idx = blockIdx.x * 256 + threadIdx.x;   // float4 index; 524288 total
    int e = idx << 2;
    int cidx = e >> 12;            // b*256 + ch
    int ch = cidx & 255, b = cidx >> 8;
    float2 st = g_stats[b * GROUPS + (ch >> 3)];
    float wv = __ldg(&gw[ch]) * st.y;
    float bb = __ldg(&gb[ch]) - st.x * wv;
    const float4 zv = ((const float4*)g_Z)[idx];
    float4 r;
    r.x = zv.x * wv + bb;
    r.y = zv.y * wv + bb;
    r.z = zv.z * wv + bb;
    r.w = zv.w * wv + bb;
    ((float4*)out)[idx] = r;
}

// ---------------- launch ----------------
extern "C" void kernel_launch(void* const* d_in, const int* in_sizes, int n_in,
                              void* d_out, int out_size) {
    const float* qf  = (const float*)d_in[0];
    const float* kf  = (const float*)d_in[1];
    const float* qw  = (const float*)d_in[2];
    const float* q_b = (const float*)d_in[3];
    const float* kw  = (const float*)d_in[4];
    const float* k_b = (const float*)d_in[5];
    const float* vw  = (const float*)d_in[6];
    const float* v_b = (const float*)d_in[7];
    const float* ow  = (const float*)d_in[8];
    const float* o_b = (const float*)d_in[9];
    const float* gnw = (const float*)d_in[10];
    const float* gnb = (const float*)d_in[11];
    float* out = (float*)d_out;

    prep_transpose<<<dim3(128, 8, 4), dim3(32, 8)>>>(qf, kf);
    prep_weights<<<768, 256>>>(qw, kw, vw);
    qkv_gemm<<<dim3(256, 3, 2), 128>>>(q_b, k_b, v_b);
    flash_attn<<<dim3(64, 8, 2), 128>>>();
    proj_gn_partial<<<dim3(8, 32, 2), 256>>>(qf, ow, o_b);
    gn_stats<<<1, 64>>>();
    gn_apply<<<2048, 256>>>(out, gnw, gnb);
}

// round 9
// speedup vs baseline: 1.0377x; 1.0377x over previous
#include <cuda_runtime.h>
#include <cuda_bf16.h>
#include <cstdint>

// Problem constants
#define BATCH 2
#define CCH   256
#define NPOS  4096      // 64*64
#define HEADS 8
#define HDIM  32
#define GROUPS 32
#define CPG   8         // channels per group
#define GN_EPS 1e-5f
#define ATT_SCALE 0.17677669529663687f  // 1/sqrt(32)
// Q pre-scale so scores are already in log2 domain: exp(x*s) = exp2(x*s*log2e)
#define QSC (0.17677669529663687f * 1.4426950408889634f)

// ---------------- scratch (device globals; no runtime allocation) ----------------
__device__ __nv_bfloat16 g_XT[2][BATCH][NPOS][CCH];      // [src(q/k)][b][n][c]  8 MB
__device__ __nv_bfloat16 g_W[3][CCH][CCH];               // q,k,v weights bf16
__device__ __nv_bfloat16 g_Q[BATCH][HEADS][NPOS][HDIM];  // 4 MB (pre-scaled by QSC)
__device__ __nv_bfloat16 g_K[BATCH][HEADS][NPOS][HDIM];  // 4 MB
__device__ __nv_bfloat16 g_V[BATCH][HEADS][HDIM][NPOS];  // transposed  4 MB
__device__ float g_AO[BATCH][CCH][NPOS];                 // attention out 8 MB
__device__ float g_Z[BATCH][CCH][NPOS];                  // residual+proj 8 MB
__device__ float2 g_part[BATCH*GROUPS][8];               // partial (sum,sumsq)
__device__ float2 g_stats[BATCH*GROUPS];                 // (mean, rstd)

// ---------------- helpers ----------------
__device__ __forceinline__ uint32_t pack_bf16x2(float lo, float hi) {
    uint32_t r;
    asm("cvt.rn.bf16x2.f32 %0, %1, %2;" : "=r"(r) : "f"(hi), "f"(lo));
    return r;
}

__device__ __forceinline__ void cp_async16(void* smem_dst, const void* gmem_src) {
    uint32_t s = (uint32_t)__cvta_generic_to_shared(smem_dst);
    asm volatile("cp.async.cg.shared.global [%0], [%1], 16;" :: "r"(s), "l"(gmem_src));
}
#define CP_COMMIT() asm volatile("cp.async.commit_group;")

#define MMA_BF16(d, a0,a1,a2,a3, b0,b1)                                   \
    asm volatile("mma.sync.aligned.m16n8k16.row.col.f32.bf16.bf16.f32 "   \
        "{%0,%1,%2,%3}, {%4,%5,%6,%7}, {%8,%9}, {%0,%1,%2,%3};"           \
        : "+f"(d[0]), "+f"(d[1]), "+f"(d[2]), "+f"(d[3])                  \
        : "r"(a0), "r"(a1), "r"(a2), "r"(a3), "r"(b0), "r"(b1))

// ---------------- kernel 1: transpose + convert inputs to bf16 ----------------
// x[b][c][n] fp32 -> g_XT[src][b][n][c] bf16
__global__ void prep_transpose(const float* __restrict__ xq, const float* __restrict__ xk) {
    __shared__ float tile[32][33];
    int src = blockIdx.z >> 1;
    int b   = blockIdx.z & 1;
    const float* x = src ? xk : xq;
    int n0 = blockIdx.x * 32, c0 = blockIdx.y * 32;
    #pragma unroll
    for (int i = 0; i < 32; i += 8)
        tile[threadIdx.y + i][threadIdx.x] =
            x[(b * CCH + c0 + threadIdx.y + i) * NPOS + n0 + threadIdx.x];
    __syncthreads();
    #pragma unroll
    for (int i = 0; i < 32; i += 8)
        g_XT[src][b][n0 + threadIdx.y + i][c0 + threadIdx.x] =
            __float2bfloat16(tile[threadIdx.x][threadIdx.y + i]);
}

// ---------------- kernel 2: convert weights to bf16 ----------------
__global__ void prep_weights(const float* __restrict__ qw,
                             const float* __restrict__ kw,
                             const float* __restrict__ vw) {
    int idx = blockIdx.x * 256 + threadIdx.x;   // grid 768 -> 196608 elements
    int which = idx >> 16;
    int r = idx & 65535;
    const float* w = (which == 0) ? qw : (which == 1) ? kw : vw;
    ((__nv_bfloat16*)g_W)[idx] = __float2bfloat16(w[r]);
}

// ---------------- kernel 3: QKV projection GEMM (bf16 mma) ----------------
// D[n][ch] = sum_c XT[n][c] * W[ch][c] + bias[ch]
__global__ __launch_bounds__(128) void qkv_gemm(const float* __restrict__ qb,
                                                const float* __restrict__ kb,
                                                const float* __restrict__ vb) {
    int p = blockIdx.y;           // 0=Q,1=K,2=V
    int b = blockIdx.z;
    int nb = blockIdx.x >> 2;     // 64 n-blocks of 64
    int cb = blockIdx.x & 3;      // 4 ch-blocks of 64
    int n0 = nb * 64, ch0 = cb * 64;
    const __nv_bfloat16* XT = &g_XT[(p == 0) ? 0 : 1][b][0][0];
    const __nv_bfloat16* W  = &g_W[p][0][0];
    const float* bias = (p == 0) ? qb : (p == 1) ? kb : vb;

    __shared__ __align__(16) __nv_bfloat16 As[64][40];  // rows n, pad to 80B
    __shared__ __align__(16) __nv_bfloat16 Bs[64][40];  // rows ch

    int tid = threadIdx.x;
    int w = tid >> 5, lane = tid & 31, g = lane >> 2, t = lane & 3;
    float acc[8][4] = {};

    for (int kk0 = 0; kk0 < 256; kk0 += 32) {
        #pragma unroll
        for (int it = 0; it < 2; it++) {
            int id2 = tid + it * 128;            // 0..255
            int r = id2 >> 2, c16 = id2 & 3;
            *(uint4*)&As[r][c16 * 8] = *(const uint4*)&XT[(n0 + r) * 256 + kk0 + c16 * 8];
            *(uint4*)&Bs[r][c16 * 8] = *(const uint4*)&W[(ch0 + r) * 256 + kk0 + c16 * 8];
        }
        __syncthreads();
        int m0 = w * 16;
        #pragma unroll
        for (int ks = 0; ks < 32; ks += 16) {
            int c = ks + 2 * t;
            uint32_t a0 = *(uint32_t*)&As[m0 + g][c];
            uint32_t a1 = *(uint32_t*)&As[m0 + g + 8][c];
            uint32_t a2 = *(uint32_t*)&As[m0 + g][c + 8];
            uint32_t a3 = *(uint32_t*)&As[m0 + g + 8][c + 8];
            #pragma unroll
            for (int j = 0; j < 8; j++) {
                uint32_t b0 = *(uint32_t*)&Bs[j * 8 + g][c];
                uint32_t b1 = *(uint32_t*)&Bs[j * 8 + g][c + 8];
                MMA_BF16(acc[j], a0, a1, a2, a3, b0, b1);
            }
        }
        __syncthreads();
    }

    // epilogue: add bias, write to head-layout scratch (Q pre-scaled to log2 domain)
    #pragma unroll
    for (int j = 0; j < 8; j++) {
        int ch = ch0 + j * 8 + 2 * t;
        float b0f = __ldg(&bias[ch]);
        float b1f = __ldg(&bias[ch + 1]);
        #pragma unroll
        for (int h2 = 0; h2 < 2; h2++) {
            int row = n0 + w * 16 + g + h2 * 8;
            float v0 = acc[j][h2 * 2 + 0] + b0f;
            float v1 = acc[j][h2 * 2 + 1] + b1f;
            int hh = ch >> 5, dd = ch & 31;
            if (p == 0) {
                *(uint32_t*)&g_Q[b][hh][row][dd] = pack_bf16x2(v0 * QSC, v1 * QSC);
            } else if (p == 1) {
                *(uint32_t*)&g_K[b][hh][row][dd] = pack_bf16x2(v0, v1);
            } else {
                g_V[b][hh][dd][row]     = __float2bfloat16(v0);
                g_V[b][hh][dd + 1][row] = __float2bfloat16(v1);
            }
        }
    }
}

// ---------------- kernel 4: flash attention ----------------
// 8 warps / CTA (M=128 q-rows), KV tiles of 64 double-buffered via cp.async,
// log2-domain online softmax (Q pre-scaled), deferred l reduction.
__global__ __launch_bounds__(256) void flash_attn() {
    int nb = blockIdx.x, h = blockIdx.y, b = blockIdx.z;
    __shared__ __align__(16) __nv_bfloat16 Ks[2][64][40];   // keys x d (pad 80B)
    __shared__ __align__(16) __nv_bfloat16 Vts[2][32][72];  // d x keys (pad 144B)

    int tid = threadIdx.x;
    int w = tid >> 5, lane = tid & 31, g = lane >> 2, t = lane & 3;
    const __nv_bfloat16* Qg = &g_Q[b][h][0][0];
    const __nv_bfloat16* Kg = &g_K[b][h][0][0];
    const __nv_bfloat16* Vg = &g_V[b][h][0][0];
    int m0 = nb * 128 + w * 16;

    // Q A-fragments (already scaled by 1/sqrt(d)*log2e), loaded once
    uint32_t qa[2][4];
    #pragma unroll
    for (int ks = 0; ks < 2; ks++) {
        int c = ks * 16 + 2 * t;
        qa[ks][0] = *(const uint32_t*)&Qg[(m0 + g) * 32 + c];
        qa[ks][1] = *(const uint32_t*)&Qg[(m0 + g + 8) * 32 + c];
        qa[ks][2] = *(const uint32_t*)&Qg[(m0 + g) * 32 + c + 8];
        qa[ks][3] = *(const uint32_t*)&Qg[(m0 + g + 8) * 32 + c + 8];
    }

    float o[4][4] = {};
    float mrow[2] = {-1e30f, -1e30f};
    float lrow[2] = {0.f, 0.f};   // per-thread partial sums; reduced at the end

    // per-thread cooperative load coords (256 threads, 256+256 uint4 per tile)
    int kr = tid >> 2, kc = (tid & 3) * 8;
    int vr = tid >> 3, vc = (tid & 7) * 8;

    // prologue: stage tile 0
    cp_async16(&Ks[0][kr][kc], &Kg[kr * 32 + kc]);
    cp_async16(&Vts[0][vr][vc], &Vg[vr * NPOS + vc]);
    CP_COMMIT();

    for (int kt = 0; kt < 64; kt++) {
        int cur = kt & 1;
        if (kt + 1 < 64) {
            int k0n = (kt + 1) * 64;
            cp_async16(&Ks[cur ^ 1][kr][kc], &Kg[(k0n + kr) * 32 + kc]);
            cp_async16(&Vts[cur ^ 1][vr][vc], &Vg[vr * NPOS + k0n + vc]);
            CP_COMMIT();
            asm volatile("cp.async.wait_group 1;");
        } else {
            asm volatile("cp.async.wait_group 0;");
        }
        __syncthreads();

        // S = Q K^T (scores already in log2 domain)
        float s[8][4] = {};
        #pragma unroll
        for (int ks = 0; ks < 2; ks++) {
            int c = ks * 16 + 2 * t;
            #pragma unroll
            for (int j = 0; j < 8; j++) {
                uint32_t b0 = *(uint32_t*)&Ks[cur][j * 8 + g][c];
                uint32_t b1 = *(uint32_t*)&Ks[cur][j * 8 + g][c + 8];
                MMA_BF16(s[j], qa[ks][0], qa[ks][1], qa[ks][2], qa[ks][3], b0, b1);
            }
        }

        // online softmax per row-half (rows g and g+8), exp2 in log2 domain
        #pragma unroll
        for (int r = 0; r < 2; r++) {
            float mx = -1e30f;
            #pragma unroll
            for (int j = 0; j < 8; j++)
                mx = fmaxf(mx, fmaxf(s[j][2 * r], s[j][2 * r + 1]));
            mx = fmaxf(mx, __shfl_xor_sync(0xffffffffu, mx, 1));
            mx = fmaxf(mx, __shfl_xor_sync(0xffffffffu, mx, 2));
            float mnew = fmaxf(mrow[r], mx);
            float corr = exp2f(mrow[r] - mnew);
            mrow[r] = mnew;
            float ls = 0.f;
            #pragma unroll
            for (int j = 0; j < 8; j++) {
                s[j][2 * r]     = exp2f(s[j][2 * r] - mnew);
                s[j][2 * r + 1] = exp2f(s[j][2 * r + 1] - mnew);
                ls += s[j][2 * r] + s[j][2 * r + 1];
            }
            lrow[r] = lrow[r] * corr + ls;   // thread-local; reduced after the loop
            #pragma unroll
            for (int dt = 0; dt < 4; dt++) {
                o[dt][2 * r]     *= corr;
                o[dt][2 * r + 1] *= corr;
            }
        }

        // O += P V   (P C-frags repacked register-locally into A-frags)
        #pragma unroll
        for (int kk = 0; kk < 4; kk++) {
            int j0 = kk * 2;
            uint32_t pa0 = pack_bf16x2(s[j0][0], s[j0][1]);
            uint32_t pa1 = pack_bf16x2(s[j0][2], s[j0][3]);
            uint32_t pa2 = pack_bf16x2(s[j0 + 1][0], s[j0 + 1][1]);
            uint32_t pa3 = pack_bf16x2(s[j0 + 1][2], s[j0 + 1][3]);
            int c = kk * 16 + 2 * t;
            #pragma unroll
            for (int dt = 0; dt < 4; dt++) {
                uint32_t b0 = *(uint32_t*)&Vts[cur][dt * 8 + g][c];
                uint32_t b1 = *(uint32_t*)&Vts[cur][dt * 8 + g][c + 8];
                MMA_BF16(o[dt], pa0, pa1, pa2, pa3, b0, b1);
            }
        }
        __syncthreads();
    }

    // final l reduction across the quad, then normalize + write
    #pragma unroll
    for (int r = 0; r < 2; r++) {
        lrow[r] += __shfl_xor_sync(0xffffffffu, lrow[r], 1);
        lrow[r] += __shfl_xor_sync(0xffffffffu, lrow[r], 2);
    }
    float inv0 = 1.f / lrow[0], inv1 = 1.f / lrow[1];
    #pragma unroll
    for (int dt = 0; dt < 4; dt++) {
        int ch = h * 32 + dt * 8 + 2 * t;
        int n = m0 + g;
        g_AO[b][ch][n]         = o[dt][0] * inv0;
        g_AO[b][ch + 1][n]     = o[dt][1] * inv0;
        g_AO[b][ch][n + 8]     = o[dt][2] * inv1;
        g_AO[b][ch + 1][n + 8] = o[dt][3] * inv1;
    }
}

// ---------------- kernel 5: out-proj + residual + partial GN stats ----------------
__global__ __launch_bounds__(256) void proj_gn_partial(const float* __restrict__ qf,
                                                       const float* __restrict__ ow,
                                                       const float* __restrict__ ob) {
    int ck = blockIdx.x;    // 8 spatial chunks of 512
    int gr = blockIdx.y;    // 32 groups
    int b  = blockIdx.z;
    __shared__ __align__(16) float ows_t[256][8];  // [i][c]
    int tid = threadIdx.x;
    for (int i = tid; i < 2048; i += 256)
        ows_t[i & 255][i >> 8] = ow[(gr * 8 + (i >> 8)) * 256 + (i & 255)];
    __syncthreads();

    int n1 = ck * 512 + tid, n2 = n1 + 256;
    float acc0[8] = {}, acc1[8] = {};
    const float* aob = &g_AO[b][0][0];
    const float4* ows4 = (const float4*)ows_t;
    #pragma unroll 4
    for (int i = 0; i < 256; i++) {
        float a1 = aob[i * NPOS + n1];
        float a2 = aob[i * NPOS + n2];
        float4 w0 = ows4[i * 2];
        float4 w1 = ows4[i * 2 + 1];
        acc0[0] += w0.x * a1; acc0[1] += w0.y * a1; acc0[2] += w0.z * a1; acc0[3] += w0.w * a1;
        acc0[4] += w1.x * a1; acc0[5] += w1.y * a1; acc0[6] += w1.z * a1; acc0[7] += w1.w * a1;
        acc1[0] += w0.x * a2; acc1[1] += w0.y * a2; acc1[2] += w0.z * a2; acc1[3] += w0.w * a2;
        acc1[4] += w1.x * a2; acc1[5] += w1.y * a2; acc1[6] += w1.z * a2; acc1[7] += w1.w * a2;
    }

    float sum = 0.f, sq = 0.f;
    #pragma unroll
    for (int c = 0; c < 8; c++) {
        int ch = gr * 8 + c;
        float bb = __ldg(&ob[ch]);
        float z1 = qf[(b * CCH + ch) * NPOS + n1] + acc0[c] + bb;
        float z2 = qf[(b * CCH + ch) * NPOS + n2] + acc1[c] + bb;
        g_Z[b][ch][n1] = z1;
        g_Z[b][ch][n2] = z2;
        sum += z1 + z2;
        sq  += z1 * z1 + z2 * z2;
    }
    // block reduce
    #pragma unroll
    for (int off = 16; off; off >>= 1) {
        sum += __shfl_xor_sync(0xffffffffu, sum, off);
        sq  += __shfl_xor_sync(0xffffffffu, sq, off);
    }
    __shared__ float2 wred[8];
    if ((tid & 31) == 0) wred[tid >> 5] = make_float2(sum, sq);
    __syncthreads();
    if (tid == 0) {
        float s = 0.f, q = 0.f;
        #pragma unroll
        for (int i = 0; i < 8; i++) { s += wred[i].x; q += wred[i].y; }
        g_part[b * GROUPS + gr][ck] = make_float2(s, q);
    }
}

// ---------------- kernel 6: finalize GN stats ----------------
__global__ void gn_stats() {
    int bg = threadIdx.x;
    if (bg < BATCH * GROUPS) {
        float s = 0.f, q = 0.f;
        #pragma unroll
        for (int c = 0; c < 8; c++) { float2 p = g_part[bg][c]; s += p.x; q += p.y; }
        const float invM = 1.f / 32768.f;
        float mean = s * invM;
        float var = q * invM - mean * mean;
        g_stats[bg] = make_float2(mean, rsqrtf(var + GN_EPS));
    }
}

// ---------------- kernel 7: apply GN ----------------
__global__ __launch_bounds__(256) void gn_apply(float* __restrict__ out,
                                                const float* __restrict__ gw,
                                                const float* __restrict__ gb) {
    int idx = blockIdx.x * 256 + threadIdx.x;   // float4 index; 524288 total
    int e = idx << 2;
    int cidx = e >> 12;            // b*256 + ch
    int ch = cidx & 255, b = cidx >> 8;
    float2 st = g_stats[b * GROUPS + (ch >> 3)];
    float wv = __ldg(&gw[ch]) * st.y;
    float bb = __ldg(&gb[ch]) - st.x * wv;
    const float4 zv = ((const float4*)g_Z)[idx];
    float4 r;
    r.x = zv.x * wv + bb;
    r.y = zv.y * wv + bb;
    r.z = zv.z * wv + bb;
    r.w = zv.w * wv + bb;
    ((float4*)out)[idx] = r;
}

// ---------------- launch ----------------
extern "C" void kernel_launch(void* const* d_in, const int* in_sizes, int n_in,
                              void* d_out, int out_size) {
    const float* qf  = (const float*)d_in[0];
    const float* kf  = (const float*)d_in[1];
    const float* qw  = (const float*)d_in[2];
    const float* q_b = (const float*)d_in[3];
    const float* kw  = (const float*)d_in[4];
    const float* k_b = (const float*)d_in[5];
    const float* vw  = (const float*)d_in[6];
    const float* v_b = (const float*)d_in[7];
    const float* ow  = (const float*)d_in[8];
    const float* o_b = (const float*)d_in[9];
    const float* gnw = (const float*)d_in[10];
    const float* gnb = (const float*)d_in[11];
    float* out = (float*)d_out;

    prep_transpose<<<dim3(128, 8, 4), dim3(32, 8)>>>(qf, kf);
    prep_weights<<<768, 256>>>(qw, kw, vw);
    qkv_gemm<<<dim3(256, 3, 2), 128>>>(q_b, k_b, v_b);
    flash_attn<<<dim3(32, 8, 2), 256>>>();
    proj_gn_partial<<<dim3(8, 32, 2), 256>>>(qf, ow, o_b);
    gn_stats<<<1, 64>>>();
    gn_apply<<<2048, 256>>>(out, gnw, gnb);
}

// round 12
// speedup vs baseline: 1.6440x; 1.5843x over previous
#include <cuda_runtime.h>
#include <cuda_bf16.h>
#include <cstdint>

// Problem constants
#define BATCH 2
#define CCH   256
#define NPOS  4096      // 64*64
#define HEADS 8
#define HDIM  32
#define GROUPS 32
#define GN_EPS 1e-5f
// Q pre-scale: exp(x/sqrt(d)) = exp2(x * (1/sqrt(d)) * log2e)
#define QSC (0.17677669529663687f * 1.4426950408889634f)

// ---------------- scratch (device globals; no runtime allocation) ----------------
__device__ __nv_bfloat16 g_XT[2][BATCH][NPOS][CCH];      // [src(q/k)][b][n][c]
__device__ __nv_bfloat16 g_W[4][CCH][CCH];               // q,k,v,out weights bf16
__device__ __nv_bfloat16 g_Q[BATCH][HEADS][NPOS][HDIM];  // pre-scaled by QSC
__device__ __nv_bfloat16 g_K[BATCH][HEADS][NPOS][HDIM];
__device__ __nv_bfloat16 g_V[BATCH][HEADS][HDIM][NPOS];  // transposed
__device__ __nv_bfloat16 g_AO[BATCH][NPOS][CCH];         // attention out, n-major bf16
__device__ float g_Z[BATCH][CCH][NPOS];                  // residual+proj fp32
__device__ float2 g_pp[BATCH][GROUPS][64];               // partial (sum,sumsq) per n-block
__device__ float2 g_stats[BATCH*GROUPS];                 // (mean, rstd)

// ---------------- helpers ----------------
__device__ __forceinline__ uint32_t pack_bf16x2(float lo, float hi) {
    uint32_t r;
    asm("cvt.rn.bf16x2.f32 %0, %1, %2;" : "=r"(r) : "f"(hi), "f"(lo));
    return r;
}
__device__ __forceinline__ float ex2(float x) {
    float y;
    asm("ex2.approx.ftz.f32 %0, %1;" : "=f"(y) : "f"(x));
    return y;
}
__device__ __forceinline__ uint32_t smem_u32(const void* p) {
    return (uint32_t)__cvta_generic_to_shared(p);
}
__device__ __forceinline__ void cp_async16(uint32_t smem_dst, const void* gmem_src) {
    asm volatile("cp.async.cg.shared.global [%0], [%1], 16;" :: "r"(smem_dst), "l"(gmem_src));
}
#define CP_COMMIT() asm volatile("cp.async.commit_group;")

__device__ __forceinline__ void ldsm_x4(uint32_t addr, uint32_t& r0, uint32_t& r1,
                                        uint32_t& r2, uint32_t& r3) {
    asm volatile("ldmatrix.sync.aligned.m8n8.x4.shared.b16 {%0,%1,%2,%3}, [%4];"
        : "=r"(r0), "=r"(r1), "=r"(r2), "=r"(r3) : "r"(addr));
}

#define MMA_BF16(d, a0,a1,a2,a3, b0,b1)                                   \
    asm volatile("mma.sync.aligned.m16n8k16.row.col.f32.bf16.bf16.f32 "   \
        "{%0,%1,%2,%3}, {%4,%5,%6,%7}, {%8,%9}, {%0,%1,%2,%3};"           \
        : "+f"(d[0]), "+f"(d[1]), "+f"(d[2]), "+f"(d[3])                  \
        : "r"(a0), "r"(a1), "r"(a2), "r"(a3), "r"(b0), "r"(b1))

// ---------------- kernel 1: transpose + convert inputs to bf16 ----------------
__global__ void prep_transpose(const float* __restrict__ xq, const float* __restrict__ xk) {
    __shared__ float tile[32][33];
    int src = blockIdx.z >> 1;
    int b   = blockIdx.z & 1;
    const float* x = src ? xk : xq;
    int n0 = blockIdx.x * 32, c0 = blockIdx.y * 32;
    #pragma unroll
    for (int i = 0; i < 32; i += 8)
        tile[threadIdx.y + i][threadIdx.x] =
            x[(b * CCH + c0 + threadIdx.y + i) * NPOS + n0 + threadIdx.x];
    __syncthreads();
    #pragma unroll
    for (int i = 0; i < 32; i += 8)
        g_XT[src][b][n0 + threadIdx.y + i][c0 + threadIdx.x] =
            __float2bfloat16(tile[threadIdx.x][threadIdx.y + i]);
}

// ---------------- kernel 2: convert weights (q,k,v,out) to bf16 ----------------
__global__ void prep_weights(const float* __restrict__ qw, const float* __restrict__ kw,
                             const float* __restrict__ vw, const float* __restrict__ ow) {
    int idx = blockIdx.x * 256 + threadIdx.x;   // grid 1024 -> 262144 elements
    int which = idx >> 16;
    int r = idx & 65535;
    const float* w = (which == 0) ? qw : (which == 1) ? kw : (which == 2) ? vw : ow;
    ((__nv_bfloat16*)g_W)[idx] = __float2bfloat16(w[r]);
}

// ---------------- kernel 3: QKV projection GEMM (bf16 mma) ----------------
__global__ __launch_bounds__(128) void qkv_gemm(const float* __restrict__ qb,
                                                const float* __restrict__ kb,
                                                const float* __restrict__ vb) {
    int p = blockIdx.y;           // 0=Q,1=K,2=V
    int b = blockIdx.z;
    int nb = blockIdx.x >> 2;
    int cb = blockIdx.x & 3;
    int n0 = nb * 64, ch0 = cb * 64;
    const __nv_bfloat16* XT = &g_XT[(p == 0) ? 0 : 1][b][0][0];
    const __nv_bfloat16* W  = &g_W[p][0][0];
    const float* bias = (p == 0) ? qb : (p == 1) ? kb : vb;

    __shared__ __align__(16) __nv_bfloat16 As[64][40];
    __shared__ __align__(16) __nv_bfloat16 Bs[64][40];

    int tid = threadIdx.x;
    int w = tid >> 5, lane = tid & 31, g = lane >> 2, t = lane & 3;
    float acc[8][4] = {};

    for (int kk0 = 0; kk0 < 256; kk0 += 32) {
        #pragma unroll
        for (int it = 0; it < 2; it++) {
            int id2 = tid + it * 128;
            int r = id2 >> 2, c16 = id2 & 3;
            *(uint4*)&As[r][c16 * 8] = *(const uint4*)&XT[(n0 + r) * 256 + kk0 + c16 * 8];
            *(uint4*)&Bs[r][c16 * 8] = *(const uint4*)&W[(ch0 + r) * 256 + kk0 + c16 * 8];
        }
        __syncthreads();
        int m0 = w * 16;
        #pragma unroll
        for (int ks = 0; ks < 32; ks += 16) {
            int c = ks + 2 * t;
            uint32_t a0 = *(uint32_t*)&As[m0 + g][c];
            uint32_t a1 = *(uint32_t*)&As[m0 + g + 8][c];
            uint32_t a2 = *(uint32_t*)&As[m0 + g][c + 8];
            uint32_t a3 = *(uint32_t*)&As[m0 + g + 8][c + 8];
            #pragma unroll
            for (int j = 0; j < 8; j++) {
                uint32_t b0 = *(uint32_t*)&Bs[j * 8 + g][c];
                uint32_t b1 = *(uint32_t*)&Bs[j * 8 + g][c + 8];
                MMA_BF16(acc[j], a0, a1, a2, a3, b0, b1);
            }
        }
        __syncthreads();
    }

    #pragma unroll
    for (int j = 0; j < 8; j++) {
        int ch = ch0 + j * 8 + 2 * t;
        float b0f = __ldg(&bias[ch]);
        float b1f = __ldg(&bias[ch + 1]);
        #pragma unroll
        for (int h2 = 0; h2 < 2; h2++) {
            int row = n0 + w * 16 + g + h2 * 8;
            float v0 = acc[j][h2 * 2 + 0] + b0f;
            float v1 = acc[j][h2 * 2 + 1] + b1f;
            int hh = ch >> 5, dd = ch & 31;
            if (p == 0) {
                *(uint32_t*)&g_Q[b][hh][row][dd] = pack_bf16x2(v0 * QSC, v1 * QSC);
            } else if (p == 1) {
                *(uint32_t*)&g_K[b][hh][row][dd] = pack_bf16x2(v0, v1);
            } else {
                g_V[b][hh][dd][row]     = __float2bfloat16(v0);
                g_V[b][hh][dd + 1][row] = __float2bfloat16(v1);
            }
        }
    }
}

// ---------------- kernel 4: flash attention ----------------
// 8 warps/CTA (M=128 q-rows), 3-stage cp.async pipeline (1 barrier/tile),
// ldmatrix fragment loads, max-free exp2 softmax (Q pre-scaled, bounded logits).
__global__ __launch_bounds__(256) void flash_attn() {
    int nb = blockIdx.x, h = blockIdx.y, b = blockIdx.z;
    __shared__ __align__(16) __nv_bfloat16 Ks[3][64][40];   // keys x d (80B rows)
    __shared__ __align__(16) __nv_bfloat16 Vts[3][32][72];  // d x keys (144B rows)
    const int KST = 64 * 80;   // 5120 B per K stage
    const int VST = 32 * 144;  // 4608 B per V stage

    int tid = threadIdx.x;
    int w = tid >> 5, lane = tid & 31, g = lane >> 2, t = lane & 3;
    const __nv_bfloat16* Qg = &g_Q[b][h][0][0];
    const __nv_bfloat16* Kg = &g_K[b][h][0][0];
    const __nv_bfloat16* Vg = &g_V[b][h][0][0];
    int m0 = nb * 128 + w * 16;

    // Q A-fragments (log2-domain pre-scaled), loaded once
    uint32_t qa[2][4];
    #pragma unroll
    for (int ks = 0; ks < 2; ks++) {
        int c = ks * 16 + 2 * t;
        qa[ks][0] = *(const uint32_t*)&Qg[(m0 + g) * 32 + c];
        qa[ks][1] = *(const uint32_t*)&Qg[(m0 + g + 8) * 32 + c];
        qa[ks][2] = *(const uint32_t*)&Qg[(m0 + g) * 32 + c + 8];
        qa[ks][3] = *(const uint32_t*)&Qg[(m0 + g + 8) * 32 + c + 8];
    }

    float o[4][4] = {};
    float lrow[2] = {0.f, 0.f};

    // cp.async cooperative coords (256 threads: 256 uint4 K + 256 uint4 V per tile)
    int kr = tid >> 2, kc = (tid & 3) * 8;
    int vr = tid >> 3, vc = (tid & 7) * 8;
    uint32_t kdst = smem_u32(&Ks[0][kr][kc]);
    uint32_t vdst = smem_u32(&Vts[0][vr][vc]);
    const __nv_bfloat16* kgp = &Kg[kr * 32 + kc];
    const __nv_bfloat16* vgp = &Vg[vr * NPOS + vc];

    // prologue: stage tiles 0,1
    cp_async16(kdst, kgp);            cp_async16(vdst, vgp);            CP_COMMIT();
    cp_async16(kdst + KST, kgp + 2048); cp_async16(vdst + VST, vgp + 64); CP_COMMIT();
    kgp += 2 * 2048; vgp += 2 * 64;

    // ldmatrix per-lane base addresses
    uint32_t ks_base = smem_u32(&Ks[0][0][0]) + (lane & 7) * 80 + (lane >> 3) * 16;
    uint32_t vs_base = smem_u32(&Vts[0][0][0]) + ((lane >> 4) * 8 + (lane & 7)) * 144
                     + ((lane >> 3) & 1) * 16;

    int rko = 0, rvo = 0;                 // read-stage byte offsets
    int wko = 2 * KST, wvo = 2 * VST;     // write-stage byte offsets

    for (int kt = 0; kt < 64; kt++) {
        if (kt < 63) asm volatile("cp.async.wait_group 1;");
        else         asm volatile("cp.async.wait_group 0;");
        __syncthreads();

        if (kt < 62) {
            cp_async16(kdst + wko, kgp);
            cp_async16(vdst + wvo, vgp);
            CP_COMMIT();
            kgp += 2048; vgp += 64;
        }

        // S = Q K^T (log2 domain)
        float s[8][4] = {};
        uint32_t ka = ks_base + rko;
        #pragma unroll
        for (int j = 0; j < 8; j++) {
            uint32_t r0, r1, r2, r3;
            ldsm_x4(ka + j * 640, r0, r1, r2, r3);
            MMA_BF16(s[j], qa[0][0], qa[0][1], qa[0][2], qa[0][3], r0, r1);
            MMA_BF16(s[j], qa[1][0], qa[1][1], qa[1][2], qa[1][3], r2, r3);
        }

        // max-free softmax numerators: P = 2^s, accumulate per-row partial sums
        float ls0 = 0.f, ls1 = 0.f;
        #pragma unroll
        for (int j = 0; j < 8; j++) {
            s[j][0] = ex2(s[j][0]); s[j][1] = ex2(s[j][1]);
            s[j][2] = ex2(s[j][2]); s[j][3] = ex2(s[j][3]);
            ls0 += s[j][0] + s[j][1];
            ls1 += s[j][2] + s[j][3];
        }
        lrow[0] += ls0; lrow[1] += ls1;

        // O += P V
        uint32_t va = vs_base + rvo;
        #pragma unroll
        for (int kk = 0; kk < 4; kk++) {
            int j0 = kk * 2;
            uint32_t pa0 = pack_bf16x2(s[j0][0], s[j0][1]);
            uint32_t pa1 = pack_bf16x2(s[j0][2], s[j0][3]);
            uint32_t pa2 = pack_bf16x2(s[j0 + 1][0], s[j0 + 1][1]);
            uint32_t pa3 = pack_bf16x2(s[j0 + 1][2], s[j0 + 1][3]);
            uint32_t r0, r1, r2, r3;
            ldsm_x4(va + kk * 32, r0, r1, r2, r3);               // dt 0,1
            MMA_BF16(o[0], pa0, pa1, pa2, pa3, r0, r1);
            MMA_BF16(o[1], pa0, pa1, pa2, pa3, r2, r3);
            ldsm_x4(va + kk * 32 + 2304, r0, r1, r2, r3);        // dt 2,3
            MMA_BF16(o[2], pa0, pa1, pa2, pa3, r0, r1);
            MMA_BF16(o[3], pa0, pa1, pa2, pa3, r2, r3);
        }

        rko += KST; if (rko == 3 * KST) rko = 0;
        rvo += VST; if (rvo == 3 * VST) rvo = 0;
        wko += KST; if (wko == 3 * KST) wko = 0;
        wvo += VST; if (wvo == 3 * VST) wvo = 0;
    }

    // reduce l across the quad, normalize, write AO as [b][n][c] bf16
    lrow[0] += __shfl_xor_sync(0xffffffffu, lrow[0], 1);
    lrow[0] += __shfl_xor_sync(0xffffffffu, lrow[0], 2);
    lrow[1] += __shfl_xor_sync(0xffffffffu, lrow[1], 1);
    lrow[1] += __shfl_xor_sync(0xffffffffu, lrow[1], 2);
    float inv0 = 1.f / lrow[0], inv1 = 1.f / lrow[1];
    int nrow = m0 + g;
    #pragma unroll
    for (int dt = 0; dt < 4; dt++) {
        int c = h * 32 + dt * 8 + 2 * t;
        *(uint32_t*)&g_AO[b][nrow][c]     = pack_bf16x2(o[dt][0] * inv0, o[dt][1] * inv0);
        *(uint32_t*)&g_AO[b][nrow + 8][c] = pack_bf16x2(o[dt][2] * inv1, o[dt][3] * inv1);
    }
}

// ---------------- kernel 5: out-proj GEMM + residual + partial GN stats ----------------
// Z[ch][n] = sum_c OW[ch][c] * AO[n][c] + ob[ch] + qf[ch][n]
__global__ __launch_bounds__(128) void proj_gemm(const float* __restrict__ qf,
                                                 const float* __restrict__ ob) {
    int b = blockIdx.z;
    int nb = blockIdx.x >> 2;     // 64 n-blocks of 64
    int cbk = blockIdx.x & 3;     // 4 ch-blocks of 64
    int n0 = nb * 64, ch0 = cbk * 64;
    const __nv_bfloat16* W  = &g_W[3][0][0];
    const __nv_bfloat16* AO = &g_AO[b][0][0];

    __shared__ __align__(16) __nv_bfloat16 As[64][40];  // rows ch
    __shared__ __align__(16) __nv_bfloat16 Bs[64][40];  // rows n

    int tid = threadIdx.x;
    int w = tid >> 5, lane = tid & 31, g = lane >> 2, t = lane & 3;
    float acc[8][4] = {};

    for (int kk0 = 0; kk0 < 256; kk0 += 32) {
        #pragma unroll
        for (int it = 0; it < 2; it++) {
            int id2 = tid + it * 128;
            int r = id2 >> 2, c16 = id2 & 3;
            *(uint4*)&As[r][c16 * 8] = *(const uint4*)&W[(ch0 + r) * 256 + kk0 + c16 * 8];
            *(uint4*)&Bs[r][c16 * 8] = *(const uint4*)&AO[(n0 + r) * 256 + kk0 + c16 * 8];
        }
        __syncthreads();
        int m0 = w * 16;
        #pragma unroll
        for (int ks = 0; ks < 32; ks += 16) {
            int c = ks + 2 * t;
            uint32_t a0 = *(uint32_t*)&As[m0 + g][c];
            uint32_t a1 = *(uint32_t*)&As[m0 + g + 8][c];
            uint32_t a2 = *(uint32_t*)&As[m0 + g][c + 8];
            uint32_t a3 = *(uint32_t*)&As[m0 + g + 8][c + 8];
            #pragma unroll
            for (int j = 0; j < 8; j++) {
                uint32_t b0 = *(uint32_t*)&Bs[j * 8 + g][c];
                uint32_t b1 = *(uint32_t*)&Bs[j * 8 + g][c + 8];
                MMA_BF16(acc[j], a0, a1, a2, a3, b0, b1);
            }
        }
        __syncthreads();
    }

    // epilogue: rows = channels, cols = n
    int chA = ch0 + w * 16 + g;
    int chB = chA + 8;
    float obA = __ldg(&ob[chA]), obB = __ldg(&ob[chB]);
    float s0 = 0.f, q0 = 0.f, s1 = 0.f, q1 = 0.f;
    #pragma unroll
    for (int j = 0; j < 8; j++) {
        int n = n0 + j * 8 + 2 * t;
        float2 rA = *(const float2*)&qf[((b << 8) + chA) * NPOS + n];
        float2 rB = *(const float2*)&qf[((b << 8) + chB) * NPOS + n];
        float z0 = acc[j][0] + obA + rA.x;
        float z1 = acc[j][1] + obA + rA.y;
        float z2 = acc[j][2] + obB + rB.x;
        float z3 = acc[j][3] + obB + rB.y;
        *(float2*)&g_Z[b][chA][n] = make_float2(z0, z1);
        *(float2*)&g_Z[b][chB][n] = make_float2(z2, z3);
        s0 += z0 + z1; q0 += z0 * z0 + z1 * z1;
        s1 += z2 + z3; q1 += z2 * z2 + z3 * z3;
    }
    // full-warp reduce (over t AND g: the 8 rows g=0..7 are one GN group)
    #pragma unroll
    for (int off = 16; off; off >>= 1) {
        s0 += __shfl_xor_sync(0xffffffffu, s0, off);
        q0 += __shfl_xor_sync(0xffffffffu, q0, off);
        s1 += __shfl_xor_sync(0xffffffffu, s1, off);
        q1 += __shfl_xor_sync(0xffffffffu, q1, off);
    }
    if (lane == 0) {
        int gr = (ch0 + w * 16) >> 3;   // rows g..g+7 -> group gr; rows +8 -> gr+1
        g_pp[b][gr][nb]     = make_float2(s0, q0);
        g_pp[b][gr + 1][nb] = make_float2(s1, q1);
    }
}

// ---------------- kernel 6: finalize GN stats ----------------
__global__ void gn_stats() {
    int bg = threadIdx.x;
    if (bg < BATCH * GROUPS) {
        int b = bg >> 5, gr = bg & 31;
        float s = 0.f, q = 0.f;
        #pragma unroll 8
        for (int i = 0; i < 64; i++) { float2 p = g_pp[b][gr][i]; s += p.x; q += p.y; }
        const float invM = 1.f / 32768.f;
        float mean = s * invM;
        float var = q * invM - mean * mean;
        g_stats[bg] = make_float2(mean, rsqrtf(var + GN_EPS));
    }
}

// ---------------- kernel 7: apply GN ----------------
__global__ __launch_bounds__(256) void gn_apply(float* __restrict__ out,
                                                const float* __restrict__ gw,
                                                const float* __restrict__ gb) {
    int idx = blockIdx.x * 256 + threadIdx.x;   // float4 index
    int e = idx << 2;
    int cidx = e >> 12;            // b*256 + ch
    int ch = cidx & 255, b = cidx >> 8;
    float2 st = g_stats[b * GROUPS + (ch >> 3)];
    float wv = __ldg(&gw[ch]) * st.y;
    float bb = __ldg(&gb[ch]) - st.x * wv;
    const float4 zv = ((const float4*)g_Z)[idx];
    float4 r;
    r.x = zv.x * wv + bb;
    r.y = zv.y * wv + bb;
    r.z = zv.z * wv + bb;
    r.w = zv.w * wv + bb;
    ((float4*)out)[idx] = r;
}

// ---------------- launch ----------------
extern "C" void kernel_launch(void* const* d_in, const int* in_sizes, int n_in,
                              void* d_out, int out_size) {
    const float* qf  = (const float*)d_in[0];
    const float* kf  = (const float*)d_in[1];
    const float* qw  = (const float*)d_in[2];
    const float* q_b = (const float*)d_in[3];
    const float* kw  = (const float*)d_in[4];
    const float* k_b = (const float*)d_in[5];
    const float* vw  = (const float*)d_in[6];
    const float* v_b = (const float*)d_in[7];
    const float* ow  = (const float*)d_in[8];
    const float* o_b = (const float*)d_in[9];
    const float* gnw = (const float*)d_in[10];
    const float* gnb = (const float*)d_in[11];
    float* out = (float*)d_out;

    prep_transpose<<<dim3(128, 8, 4), dim3(32, 8)>>>(qf, kf);
    prep_weights<<<1024, 256>>>(qw, kw, vw, ow);
    qkv_gemm<<<dim3(256, 3, 2), 128>>>(q_b, k_b, v_b);
    flash_attn<<<dim3(32, 8, 2), 256>>>();
    proj_gemm<<<dim3(256, 1, 2), 128>>>(qf, o_b);
    gn_stats<<<1, 64>>>();
    gn_apply<<<2048, 256>>>(out, gnw, gnb);
}

// round 13
// speedup vs baseline: 1.6465x; 1.0015x over previous
#include <cuda_runtime.h>
#include <cuda_bf16.h>
#include <cstdint>

// Problem constants
#define BATCH 2
#define CCH   256
#define NPOS  4096      // 64*64
#define HEADS 8
#define HDIM  32
#define GROUPS 32
#define GN_EPS 1e-5f
// Q pre-scale: exp(x/sqrt(d)) = exp2(x * (1/sqrt(d)) * log2e)
#define QSC (0.17677669529663687f * 1.4426950408889634f)

// ---------------- scratch (device globals; no runtime allocation) ----------------
__device__ __nv_bfloat16 g_XT[2][BATCH][NPOS][CCH];      // [src(q/k)][b][n][c]
__device__ __nv_bfloat16 g_W[4][CCH][CCH];               // q,k,v,out weights bf16
__device__ __nv_bfloat16 g_Q[BATCH][HEADS][NPOS][HDIM];  // pre-scaled by QSC
__device__ __nv_bfloat16 g_K[BATCH][HEADS][NPOS][HDIM];
__device__ __nv_bfloat16 g_V[BATCH][HEADS][HDIM][NPOS];  // transposed
__device__ __nv_bfloat16 g_AO[BATCH][NPOS][CCH];         // attention out, n-major bf16
__device__ float g_Z[BATCH][CCH][NPOS];                  // residual+proj fp32
__device__ float2 g_pp[BATCH][GROUPS][64];               // partial (sum,sumsq) per n-block
__device__ float2 g_stats[BATCH*GROUPS];                 // (mean, rstd)

// ---------------- helpers ----------------
__device__ __forceinline__ uint32_t pack_bf16x2(float lo, float hi) {
    uint32_t r;
    asm("cvt.rn.bf16x2.f32 %0, %1, %2;" : "=r"(r) : "f"(hi), "f"(lo));
    return r;
}
__device__ __forceinline__ float ex2(float x) {
    float y;
    asm("ex2.approx.ftz.f32 %0, %1;" : "=f"(y) : "f"(x));
    return y;
}
__device__ __forceinline__ uint32_t smem_u32(const void* p) {
    return (uint32_t)__cvta_generic_to_shared(p);
}
__device__ __forceinline__ void cp_async16(uint32_t smem_dst, const void* gmem_src) {
    asm volatile("cp.async.cg.shared.global [%0], [%1], 16;" :: "r"(smem_dst), "l"(gmem_src));
}
#define CP_COMMIT() asm volatile("cp.async.commit_group;")

__device__ __forceinline__ void ldsm_x4(uint32_t addr, uint32_t& r0, uint32_t& r1,
                                        uint32_t& r2, uint32_t& r3) {
    asm volatile("ldmatrix.sync.aligned.m8n8.x4.shared.b16 {%0,%1,%2,%3}, [%4];"
        : "=r"(r0), "=r"(r1), "=r"(r2), "=r"(r3) : "r"(addr));
}

#define MMA_BF16(d, a0,a1,a2,a3, b0,b1)                                   \
    asm volatile("mma.sync.aligned.m16n8k16.row.col.f32.bf16.bf16.f32 "   \
        "{%0,%1,%2,%3}, {%4,%5,%6,%7}, {%8,%9}, {%0,%1,%2,%3};"           \
        : "+f"(d[0]), "+f"(d[1]), "+f"(d[2]), "+f"(d[3])                  \
        : "r"(a0), "r"(a1), "r"(a2), "r"(a3), "r"(b0), "r"(b1))

// ---------------- kernel 1: transpose + convert inputs to bf16 ----------------
__global__ void prep_transpose(const float* __restrict__ xq, const float* __restrict__ xk) {
    __shared__ float tile[32][33];
    int src = blockIdx.z >> 1;
    int b   = blockIdx.z & 1;
    const float* x = src ? xk : xq;
    int n0 = blockIdx.x * 32, c0 = blockIdx.y * 32;
    #pragma unroll
    for (int i = 0; i < 32; i += 8)
        tile[threadIdx.y + i][threadIdx.x] =
            x[(b * CCH + c0 + threadIdx.y + i) * NPOS + n0 + threadIdx.x];
    __syncthreads();
    #pragma unroll
    for (int i = 0; i < 32; i += 8)
        g_XT[src][b][n0 + threadIdx.y + i][c0 + threadIdx.x] =
            __float2bfloat16(tile[threadIdx.x][threadIdx.y + i]);
}

// ---------------- kernel 2: convert weights (q,k,v,out) to bf16 ----------------
__global__ void prep_weights(const float* __restrict__ qw, const float* __restrict__ kw,
                             const float* __restrict__ vw, const float* __restrict__ ow) {
    int idx = blockIdx.x * 256 + threadIdx.x;   // grid 1024 -> 262144 elements
    int which = idx >> 16;
    int r = idx & 65535;
    const float* w = (which == 0) ? qw : (which == 1) ? kw : (which == 2) ? vw : ow;
    ((__nv_bfloat16*)g_W)[idx] = __float2bfloat16(w[r]);
}

// ---------------- kernel 3: QKV projection GEMM (bf16 mma) ----------------
__global__ __launch_bounds__(128) void qkv_gemm(const float* __restrict__ qb,
                                                const float* __restrict__ kb,
                                                const float* __restrict__ vb) {
    int p = blockIdx.y;           // 0=Q,1=K,2=V
    int b = blockIdx.z;
    int nb = blockIdx.x >> 2;
    int cb = blockIdx.x & 3;
    int n0 = nb * 64, ch0 = cb * 64;
    const __nv_bfloat16* XT = &g_XT[(p == 0) ? 0 : 1][b][0][0];
    const __nv_bfloat16* W  = &g_W[p][0][0];
    const float* bias = (p == 0) ? qb : (p == 1) ? kb : vb;

    __shared__ __align__(16) __nv_bfloat16 As[64][40];
    __shared__ __align__(16) __nv_bfloat16 Bs[64][40];

    int tid = threadIdx.x;
    int w = tid >> 5, lane = tid & 31, g = lane >> 2, t = lane & 3;
    float acc[8][4] = {};

    for (int kk0 = 0; kk0 < 256; kk0 += 32) {
        #pragma unroll
        for (int it = 0; it < 2; it++) {
            int id2 = tid + it * 128;
            int r = id2 >> 2, c16 = id2 & 3;
            *(uint4*)&As[r][c16 * 8] = *(const uint4*)&XT[(n0 + r) * 256 + kk0 + c16 * 8];
            *(uint4*)&Bs[r][c16 * 8] = *(const uint4*)&W[(ch0 + r) * 256 + kk0 + c16 * 8];
        }
        __syncthreads();
        int m0 = w * 16;
        #pragma unroll
        for (int ks = 0; ks < 32; ks += 16) {
            int c = ks + 2 * t;
            uint32_t a0 = *(uint32_t*)&As[m0 + g][c];
            uint32_t a1 = *(uint32_t*)&As[m0 + g + 8][c];
            uint32_t a2 = *(uint32_t*)&As[m0 + g][c + 8];
            uint32_t a3 = *(uint32_t*)&As[m0 + g + 8][c + 8];
            #pragma unroll
            for (int j = 0; j < 8; j++) {
                uint32_t b0 = *(uint32_t*)&Bs[j * 8 + g][c];
                uint32_t b1 = *(uint32_t*)&Bs[j * 8 + g][c + 8];
                MMA_BF16(acc[j], a0, a1, a2, a3, b0, b1);
            }
        }
        __syncthreads();
    }

    #pragma unroll
    for (int j = 0; j < 8; j++) {
        int ch = ch0 + j * 8 + 2 * t;
        float b0f = __ldg(&bias[ch]);
        float b1f = __ldg(&bias[ch + 1]);
        #pragma unroll
        for (int h2 = 0; h2 < 2; h2++) {
            int row = n0 + w * 16 + g + h2 * 8;
            float v0 = acc[j][h2 * 2 + 0] + b0f;
            float v1 = acc[j][h2 * 2 + 1] + b1f;
            int hh = ch >> 5, dd = ch & 31;
            if (p == 0) {
                *(uint32_t*)&g_Q[b][hh][row][dd] = pack_bf16x2(v0 * QSC, v1 * QSC);
            } else if (p == 1) {
                *(uint32_t*)&g_K[b][hh][row][dd] = pack_bf16x2(v0, v1);
            } else {
                g_V[b][hh][dd][row]     = __float2bfloat16(v0);
                g_V[b][hh][dd + 1][row] = __float2bfloat16(v1);
            }
        }
    }
}

// ---------------- kernel 4: flash attention ----------------
// 8 warps/CTA (M=128 q-rows), 3-stage cp.async pipeline (1 barrier/tile),
// ldmatrix fragment loads, max-free exp2 softmax (Q pre-scaled, bounded logits).
__global__ __launch_bounds__(256) void flash_attn() {
    int nb = blockIdx.x, h = blockIdx.y, b = blockIdx.z;
    __shared__ __align__(16) __nv_bfloat16 Ks[3][64][40];   // keys x d (80B rows)
    __shared__ __align__(16) __nv_bfloat16 Vts[3][32][72];  // d x keys (144B rows)
    const int KST = 64 * 80;   // 5120 B per K stage
    const int VST = 32 * 144;  // 4608 B per V stage

    int tid = threadIdx.x;
    int w = tid >> 5, lane = tid & 31, g = lane >> 2, t = lane & 3;
    const __nv_bfloat16* Qg = &g_Q[b][h][0][0];
    const __nv_bfloat16* Kg = &g_K[b][h][0][0];
    const __nv_bfloat16* Vg = &g_V[b][h][0][0];
    int m0 = nb * 128 + w * 16;

    // Q A-fragments (log2-domain pre-scaled), loaded once
    uint32_t qa[2][4];
    #pragma unroll
    for (int ks = 0; ks < 2; ks++) {
        int c = ks * 16 + 2 * t;
        qa[ks][0] = *(const uint32_t*)&Qg[(m0 + g) * 32 + c];
        qa[ks][1] = *(const uint32_t*)&Qg[(m0 + g + 8) * 32 + c];
        qa[ks][2] = *(const uint32_t*)&Qg[(m0 + g) * 32 + c + 8];
        qa[ks][3] = *(const uint32_t*)&Qg[(m0 + g + 8) * 32 + c + 8];
    }

    float o[4][4] = {};
    float lrow[2] = {0.f, 0.f};

    // cp.async cooperative coords (256 threads: 256 uint4 K + 256 uint4 V per tile)
    int kr = tid >> 2, kc = (tid & 3) * 8;
    int vr = tid >> 3, vc = (tid & 7) * 8;
    uint32_t kdst = smem_u32(&Ks[0][kr][kc]);
    uint32_t vdst = smem_u32(&Vts[0][vr][vc]);
    const __nv_bfloat16* kgp = &Kg[kr * 32 + kc];
    const __nv_bfloat16* vgp = &Vg[vr * NPOS + vc];

    // prologue: stage tiles 0,1
    cp_async16(kdst, kgp);            cp_async16(vdst, vgp);            CP_COMMIT();
    cp_async16(kdst + KST, kgp + 2048); cp_async16(vdst + VST, vgp + 64); CP_COMMIT();
    kgp += 2 * 2048; vgp += 2 * 64;

    // ldmatrix per-lane base addresses
    uint32_t ks_base = smem_u32(&Ks[0][0][0]) + (lane & 7) * 80 + (lane >> 3) * 16;
    uint32_t vs_base = smem_u32(&Vts[0][0][0]) + ((lane >> 4) * 8 + (lane & 7)) * 144
                     + ((lane >> 3) & 1) * 16;

    int rko = 0, rvo = 0;                 // read-stage byte offsets
    int wko = 2 * KST, wvo = 2 * VST;     // write-stage byte offsets

    for (int kt = 0; kt < 64; kt++) {
        if (kt < 63) asm volatile("cp.async.wait_group 1;");
        else         asm volatile("cp.async.wait_group 0;");
        __syncthreads();

        if (kt < 62) {
            cp_async16(kdst + wko, kgp);
            cp_async16(vdst + wvo, vgp);
            CP_COMMIT();
            kgp += 2048; vgp += 64;
        }

        // S = Q K^T (log2 domain)
        float s[8][4] = {};
        uint32_t ka = ks_base + rko;
        #pragma unroll
        for (int j = 0; j < 8; j++) {
            uint32_t r0, r1, r2, r3;
            ldsm_x4(ka + j * 640, r0, r1, r2, r3);
            MMA_BF16(s[j], qa[0][0], qa[0][1], qa[0][2], qa[0][3], r0, r1);
            MMA_BF16(s[j], qa[1][0], qa[1][1], qa[1][2], qa[1][3], r2, r3);
        }

        // max-free softmax numerators: P = 2^s, accumulate per-row partial sums
        float ls0 = 0.f, ls1 = 0.f;
        #pragma unroll
        for (int j = 0; j < 8; j++) {
            s[j][0] = ex2(s[j][0]); s[j][1] = ex2(s[j][1]);
            s[j][2] = ex2(s[j][2]); s[j][3] = ex2(s[j][3]);
            ls0 += s[j][0] + s[j][1];
            ls1 += s[j][2] + s[j][3];
        }
        lrow[0] += ls0; lrow[1] += ls1;

        // O += P V
        uint32_t va = vs_base + rvo;
        #pragma unroll
        for (int kk = 0; kk < 4; kk++) {
            int j0 = kk * 2;
            uint32_t pa0 = pack_bf16x2(s[j0][0], s[j0][1]);
            uint32_t pa1 = pack_bf16x2(s[j0][2], s[j0][3]);
            uint32_t pa2 = pack_bf16x2(s[j0 + 1][0], s[j0 + 1][1]);
            uint32_t pa3 = pack_bf16x2(s[j0 + 1][2], s[j0 + 1][3]);
            uint32_t r0, r1, r2, r3;
            ldsm_x4(va + kk * 32, r0, r1, r2, r3);               // dt 0,1
            MMA_BF16(o[0], pa0, pa1, pa2, pa3, r0, r1);
            MMA_BF16(o[1], pa0, pa1, pa2, pa3, r2, r3);
            ldsm_x4(va + kk * 32 + 2304, r0, r1, r2, r3);        // dt 2,3
            MMA_BF16(o[2], pa0, pa1, pa2, pa3, r0, r1);
            MMA_BF16(o[3], pa0, pa1, pa2, pa3, r2, r3);
        }

        rko += KST; if (rko == 3 * KST) rko = 0;
        rvo += VST; if (rvo == 3 * VST) rvo = 0;
        wko += KST; if (wko == 3 * KST) wko = 0;
        wvo += VST; if (wvo == 3 * VST) wvo = 0;
    }

    // reduce l across the quad, normalize, write AO as [b][n][c] bf16
    lrow[0] += __shfl_xor_sync(0xffffffffu, lrow[0], 1);
    lrow[0] += __shfl_xor_sync(0xffffffffu, lrow[0], 2);
    lrow[1] += __shfl_xor_sync(0xffffffffu, lrow[1], 1);
    lrow[1] += __shfl_xor_sync(0xffffffffu, lrow[1], 2);
    float inv0 = 1.f / lrow[0], inv1 = 1.f / lrow[1];
    int nrow = m0 + g;
    #pragma unroll
    for (int dt = 0; dt < 4; dt++) {
        int c = h * 32 + dt * 8 + 2 * t;
        *(uint32_t*)&g_AO[b][nrow][c]     = pack_bf16x2(o[dt][0] * inv0, o[dt][1] * inv0);
        *(uint32_t*)&g_AO[b][nrow + 8][c] = pack_bf16x2(o[dt][2] * inv1, o[dt][3] * inv1);
    }
}

// ---------------- kernel 5: out-proj GEMM + residual + partial GN stats ----------------
// Z[ch][n] = sum_c OW[ch][c] * AO[n][c] + ob[ch] + qf[ch][n]
__global__ __launch_bounds__(128) void proj_gemm(const float* __restrict__ qf,
                                                 const float* __restrict__ ob) {
    int b = blockIdx.z;
    int nb = blockIdx.x >> 2;     // 64 n-blocks of 64
    int cbk = blockIdx.x & 3;     // 4 ch-blocks of 64
    int n0 = nb * 64, ch0 = cbk * 64;
    const __nv_bfloat16* W  = &g_W[3][0][0];
    const __nv_bfloat16* AO = &g_AO[b][0][0];

    __shared__ __align__(16) __nv_bfloat16 As[64][40];  // rows ch
    __shared__ __align__(16) __nv_bfloat16 Bs[64][40];  // rows n

    int tid = threadIdx.x;
    int w = tid >> 5, lane = tid & 31, g = lane >> 2, t = lane & 3;
    float acc[8][4] = {};

    for (int kk0 = 0; kk0 < 256; kk0 += 32) {
        #pragma unroll
        for (int it = 0; it < 2; it++) {
            int id2 = tid + it * 128;
            int r = id2 >> 2, c16 = id2 & 3;
            *(uint4*)&As[r][c16 * 8] = *(const uint4*)&W[(ch0 + r) * 256 + kk0 + c16 * 8];
            *(uint4*)&Bs[r][c16 * 8] = *(const uint4*)&AO[(n0 + r) * 256 + kk0 + c16 * 8];
        }
        __syncthreads();
        int m0 = w * 16;
        #pragma unroll
        for (int ks = 0; ks < 32; ks += 16) {
            int c = ks + 2 * t;
            uint32_t a0 = *(uint32_t*)&As[m0 + g][c];
            uint32_t a1 = *(uint32_t*)&As[m0 + g + 8][c];
            uint32_t a2 = *(uint32_t*)&As[m0 + g][c + 8];
            uint32_t a3 = *(uint32_t*)&As[m0 + g + 8][c + 8];
            #pragma unroll
            for (int j = 0; j < 8; j++) {
                uint32_t b0 = *(uint32_t*)&Bs[j * 8 + g][c];
                uint32_t b1 = *(uint32_t*)&Bs[j * 8 + g][c + 8];
                MMA_BF16(acc[j], a0, a1, a2, a3, b0, b1);
            }
        }
        __syncthreads();
    }

    // epilogue: rows = channels, cols = n
    int chA = ch0 + w * 16 + g;
    int chB = chA + 8;
    float obA = __ldg(&ob[chA]), obB = __ldg(&ob[chB]);
    float s0 = 0.f, q0 = 0.f, s1 = 0.f, q1 = 0.f;
    #pragma unroll
    for (int j = 0; j < 8; j++) {
        int n = n0 + j * 8 + 2 * t;
        float2 rA = *(const float2*)&qf[((b << 8) + chA) * NPOS + n];
        float2 rB = *(const float2*)&qf[((b << 8) + chB) * NPOS + n];
        float z0 = acc[j][0] + obA + rA.x;
        float z1 = acc[j][1] + obA + rA.y;
        float z2 = acc[j][2] + obB + rB.x;
        float z3 = acc[j][3] + obB + rB.y;
        *(float2*)&g_Z[b][chA][n] = make_float2(z0, z1);
        *(float2*)&g_Z[b][chB][n] = make_float2(z2, z3);
        s0 += z0 + z1; q0 += z0 * z0 + z1 * z1;
        s1 += z2 + z3; q1 += z2 * z2 + z3 * z3;
    }
    // full-warp reduce (over t AND g: the 8 rows g=0..7 are one GN group)
    #pragma unroll
    for (int off = 16; off; off >>= 1) {
        s0 += __shfl_xor_sync(0xffffffffu, s0, off);
        q0 += __shfl_xor_sync(0xffffffffu, q0, off);
        s1 += __shfl_xor_sync(0xffffffffu, s1, off);
        q1 += __shfl_xor_sync(0xffffffffu, q1, off);
    }
    if (lane == 0) {
        int gr = (ch0 + w * 16) >> 3;   // rows g..g+7 -> group gr; rows +8 -> gr+1
        g_pp[b][gr][nb]     = make_float2(s0, q0);
        g_pp[b][gr + 1][nb] = make_float2(s1, q1);
    }
}

// ---------------- kernel 6: finalize GN stats ----------------
__global__ void gn_stats() {
    int bg = threadIdx.x;
    if (bg < BATCH * GROUPS) {
        int b = bg >> 5, gr = bg & 31;
        float s = 0.f, q = 0.f;
        #pragma unroll 8
        for (int i = 0; i < 64; i++) { float2 p = g_pp[b][gr][i]; s += p.x; q += p.y; }
        const float invM = 1.f / 32768.f;
        float mean = s * invM;
        float var = q * invM - mean * mean;
        g_stats[bg] = make_float2(mean, rsqrtf(var + GN_EPS));
    }
}

// ---------------- kernel 7: apply GN ----------------
__global__ __launch_bounds__(256) void gn_apply(float* __restrict__ out,
                                                const float* __restrict__ gw,
                                                const float* __restrict__ gb) {
    int idx = blockIdx.x * 256 + threadIdx.x;   // float4 index
    int e = idx << 2;
    int cidx = e >> 12;            // b*256 + ch
    int ch = cidx & 255, b = cidx >> 8;
    float2 st = g_stats[b * GROUPS + (ch >> 3)];
    float wv = __ldg(&gw[ch]) * st.y;
    float bb = __ldg(&gb[ch]) - st.x * wv;
    const float4 zv = ((const float4*)g_Z)[idx];
    float4 r;
    r.x = zv.x * wv + bb;
    r.y = zv.y * wv + bb;
    r.z = zv.z * wv + bb;
    r.w = zv.w * wv + bb;
    ((float4*)out)[idx] = r;
}

// ---------------- launch ----------------
extern "C" void kernel_launch(void* const* d_in, const int* in_sizes, int n_in,
                              void* d_out, int out_size) {
    const float* qf  = (const float*)d_in[0];
    const float* kf  = (const float*)d_in[1];
    const float* qw  = (const float*)d_in[2];
    const float* q_b = (const float*)d_in[3];
    const float* kw  = (const float*)d_in[4];
    const float* k_b = (const float*)d_in[5];
    const float* vw  = (const float*)d_in[6];
    const float* v_b = (const float*)d_in[7];
    const float* ow  = (const float*)d_in[8];
    const float* o_b = (const float*)d_in[9];
    const float* gnw = (const float*)d_in[10];
    const float* gnb = (const float*)d_in[11];
    float* out = (float*)d_out;

    prep_transpose<<<dim3(128, 8, 4), dim3(32, 8)>>>(qf, kf);
    prep_weights<<<1024, 256>>>(qw, kw, vw, ow);
    qkv_gemm<<<dim3(256, 3, 2), 128>>>(q_b, k_b, v_b);
    flash_attn<<<dim3(32, 8, 2), 256>>>();
    proj_gemm<<<dim3(256, 1, 2), 128>>>(qf, o_b);
    gn_stats<<<1, 64>>>();
    gn_apply<<<2048, 256>>>(out, gnw, gnb);
}